// round 1
// baseline (speedup 1.0000x reference)
#include <cuda_runtime.h>

// Problem constants (N_ATOMS = 128, fixed by the reference)
#define NA      128
#define NSEG    7875          // sum_{i=0}^{124} (125 - i)
#define PADLEN  8128          // M + 2 = (n^2-n)/2
#define OUTPB   16256         // 2 * PADLEN
#define MAXB    512

// Scratch: per-(batch, segment) writhe values (~16.1 MB)
__device__ float g_wr[MAXB * NSEG];

// off(i) = number of segments with first index < i  (n = 128)
__device__ __forceinline__ int seg_off(int i) { return (i * (251 - i)) >> 1; }
// start(a) = pair index pidx(a, a+1)  (n = 128)
__device__ __forceinline__ int pair_start(int a) { return (a * (255 - a)) >> 1; }

// -------------------------------------------------------------------------
// Kernel 1: writhe per (batch, segment)
// -------------------------------------------------------------------------
__global__ __launch_bounds__(256) void writhe_kernel(const float* __restrict__ xyz)
{
    __shared__ float sx[NA], sy[NA], sz[NA];
    const int b = blockIdx.y;
    const float* x = xyz + (size_t)b * NA * 3;
    for (int t = threadIdx.x; t < NA; t += blockDim.x) {
        sx[t] = x[3 * t + 0];
        sy[t] = x[3 * t + 1];
        sz[t] = x[3 * t + 2];
    }
    __syncthreads();

    const int s = blockIdx.x * blockDim.x + threadIdx.x;
    if (s >= NSEG) return;

    // invert s -> (i, j):  largest i with seg_off(i) <= s
    int i = (int)((251.0f - sqrtf(63001.0f - 8.0f * (float)s)) * 0.5f);
    if (i < 0) i = 0;
    if (i > 124) i = 124;
    while (i < 124 && seg_off(i + 1) <= s) i++;
    while (i > 0 && seg_off(i) > s) i--;
    const int j = s - seg_off(i) + i + 2;

    const float p0x = sx[i],     p0y = sy[i],     p0z = sz[i];
    const float p1x = sx[i + 1], p1y = sy[i + 1], p1z = sz[i + 1];
    const float p2x = sx[j],     p2y = sy[j],     p2z = sz[j];
    const float p3x = sx[j + 1], p3y = sy[j + 1], p3z = sz[j + 1];

    // unnormalized direction vectors (normalization is redundant: the crosses
    // are renormalized and only the sign of dot(axial, d0) matters)
    const float d0x = p2x - p0x, d0y = p2y - p0y, d0z = p2z - p0z;
    const float d1x = p3x - p0x, d1y = p3y - p0y, d1z = p3z - p0z;
    const float d2x = p2x - p1x, d2y = p2y - p1y, d2z = p2z - p1z;
    const float d3x = p3x - p1x, d3y = p3y - p1y, d3z = p3z - p1z;

    // axial = cross(p3 - p2, p1 - p0)
    const float ex = p3x - p2x, ey = p3y - p2y, ez = p3z - p2z;
    const float fx = p1x - p0x, fy = p1y - p0y, fz = p1z - p0z;
    const float axx = ey * fz - ez * fy;
    const float axy = ez * fx - ex * fz;
    const float axz = ex * fy - ey * fx;
    const float dp  = axx * d0x + axy * d0y + axz * d0z;
    const float sg  = (dp > 0.0f) ? 1.0f : ((dp < 0.0f) ? -1.0f : 0.0f);

    // c0 = d0 x d1, c1 = d1 x d3, c2 = d3 x d2, c3 = d2 x d0
    const float c0x = d0y * d1z - d0z * d1y;
    const float c0y = d0z * d1x - d0x * d1z;
    const float c0z = d0x * d1y - d0y * d1x;

    const float c1x = d1y * d3z - d1z * d3y;
    const float c1y = d1z * d3x - d1x * d3z;
    const float c1z = d1x * d3y - d1y * d3x;

    const float c2x = d3y * d2z - d3z * d2y;
    const float c2y = d3z * d2x - d3x * d2z;
    const float c2z = d3x * d2y - d3y * d2x;

    const float c3x = d2y * d0z - d2z * d0y;
    const float c3y = d2z * d0x - d2x * d0z;
    const float c3z = d2x * d0y - d2y * d0x;

    const float r0 = rsqrtf(c0x * c0x + c0y * c0y + c0z * c0z);
    const float r1 = rsqrtf(c1x * c1x + c1y * c1y + c1z * c1z);
    const float r2 = rsqrtf(c2x * c2x + c2y * c2y + c2z * c2z);
    const float r3 = rsqrtf(c3x * c3x + c3y * c3y + c3z * c3z);

    float q0 = (c0x * c1x + c0y * c1y + c0z * c1z) * r0 * r1;
    float q1 = (c1x * c2x + c1y * c2y + c1z * c2z) * r1 * r2;
    float q2 = (c2x * c3x + c2y * c3y + c2z * c3z) * r2 * r3;
    float q3 = (c3x * c0x + c3y * c0y + c3z * c0z) * r3 * r0;

    q0 = fminf(fmaxf(q0, -1.0f), 1.0f);
    q1 = fminf(fmaxf(q1, -1.0f), 1.0f);
    q2 = fminf(fmaxf(q2, -1.0f), 1.0f);
    q3 = fminf(fmaxf(q3, -1.0f), 1.0f);

    const float omega = asinf(q0) + asinf(q1) + asinf(q2) + asinf(q3);

    g_wr[(size_t)b * NSEG + s] = omega * sg * 0.15915494309189535f; // 1/(2*pi)
}

// -------------------------------------------------------------------------
// Kernel 2: output gather. out[b,k] = padded_concat[b, sort[k]], where
// triu[t] = sum of wr over segments {(a,bb),(a,bb-1),(a-1,bb),(a-1,bb-1)}
// with (a,bb) = inverse of t = pidx(a,bb) - 1.
// -------------------------------------------------------------------------
__device__ __forceinline__ float segval(const float* __restrict__ w, int i, int j)
{
    if (i < 0 || i > NA - 4 || j < i + 2 || j > NA - 2) return 0.0f;
    return __ldg(&w[seg_off(i) + (j - i - 2)]);
}

__global__ __launch_bounds__(256) void gather_kernel(const int* __restrict__ sort,
                                                     float* __restrict__ out)
{
    const int k = blockIdx.x * blockDim.x + threadIdx.x;
    const int b = blockIdx.y;
    if (k >= OUTPB) return;

    const int v  = sort[k];
    const int vm = (v >= PADLEN) ? v - PADLEN : v;

    float r = 0.0f;
    if (vm > 0 && vm < PADLEN - 1) {
        const int u = vm; // u = t + 1 = pidx(a, bb)
        int a = (int)((255.0f - sqrtf(65025.0f - 8.0f * (float)u)) * 0.5f);
        if (a < 0) a = 0;
        if (a > 125) a = 125;
        while (a < 125 && pair_start(a + 1) <= u) a++;
        while (a > 0 && pair_start(a) > u) a--;
        const int bb = u - pair_start(a) + a + 1;

        const float* w = g_wr + (size_t)b * NSEG;
        r = segval(w, a, bb) + segval(w, a, bb - 1) +
            segval(w, a - 1, bb) + segval(w, a - 1, bb - 1);
    }
    out[(size_t)b * OUTPB + k] = r;
}

// -------------------------------------------------------------------------
extern "C" void kernel_launch(void* const* d_in, const int* in_sizes, int n_in,
                              void* d_out, int out_size)
{
    const float* xyz  = (const float*)d_in[0];
    const int*   sort = (const int*)d_in[3];
    int B = in_sizes[0] / (NA * 3);
    if (B > MAXB) B = MAXB;

    dim3 gw((NSEG + 255) / 256, B);
    writhe_kernel<<<gw, 256>>>(xyz);

    dim3 gg((OUTPB + 255) / 256, B);
    gather_kernel<<<gg, 256>>>(sort, (float*)d_out);
}

// round 2
// speedup vs baseline: 1.2485x; 1.2485x over previous
#include <cuda_runtime.h>

// Problem constants (N_ATOMS = 128, fixed by the reference)
#define NA      128
#define NSEG    7875          // sum_{i=0}^{124} (125 - i)
#define OUTPB   16256         // n^2 - n  (all off-diagonal cells, row-major)
#define MAXB    512
#define SDIM    130           // padded symmetric matrix: index (x+1, y+1), zero border

// Scratch: per-batch padded symmetric segment-writhe matrix (~34.6 MB).
// Zero-initialized at module load; invalid entries are NEVER written, so the
// zero border / zero invalid cells are permanent and deterministic.
__device__ float g_S[(size_t)MAXB * SDIM * SDIM];

// off(i) = number of segments with first index < i  (n = 128)
__device__ __forceinline__ int seg_off(int i) { return (i * (251 - i)) >> 1; }

// -------------------------------------------------------------------------
// Kernel 1: writhe per (batch, segment); store symmetric into padded S
// -------------------------------------------------------------------------
__global__ __launch_bounds__(256) void writhe_kernel(const float* __restrict__ xyz)
{
    __shared__ float sx[NA], sy[NA], sz[NA];
    const int b = blockIdx.y;
    const float* x = xyz + (size_t)b * NA * 3;
    for (int t = threadIdx.x; t < NA; t += blockDim.x) {
        sx[t] = x[3 * t + 0];
        sy[t] = x[3 * t + 1];
        sz[t] = x[3 * t + 2];
    }
    __syncthreads();

    const int s = blockIdx.x * blockDim.x + threadIdx.x;
    if (s >= NSEG) return;

    // invert s -> (i, j):  largest i with seg_off(i) <= s
    int i = (int)((251.0f - sqrtf(63001.0f - 8.0f * (float)s)) * 0.5f);
    if (i < 0) i = 0;
    if (i > 124) i = 124;
    while (i < 124 && seg_off(i + 1) <= s) i++;
    while (i > 0 && seg_off(i) > s) i--;
    const int j = s - seg_off(i) + i + 2;

    const float p0x = sx[i],     p0y = sy[i],     p0z = sz[i];
    const float p1x = sx[i + 1], p1y = sy[i + 1], p1z = sz[i + 1];
    const float p2x = sx[j],     p2y = sy[j],     p2z = sz[j];
    const float p3x = sx[j + 1], p3y = sy[j + 1], p3z = sz[j + 1];

    // unnormalized direction vectors (normalization is redundant: the crosses
    // are renormalized and only the sign of dot(axial, d0) matters)
    const float d0x = p2x - p0x, d0y = p2y - p0y, d0z = p2z - p0z;
    const float d1x = p3x - p0x, d1y = p3y - p0y, d1z = p3z - p0z;
    const float d2x = p2x - p1x, d2y = p2y - p1y, d2z = p2z - p1z;
    const float d3x = p3x - p1x, d3y = p3y - p1y, d3z = p3z - p1z;

    // axial = cross(p3 - p2, p1 - p0)
    const float ex = p3x - p2x, ey = p3y - p2y, ez = p3z - p2z;
    const float fx = p1x - p0x, fy = p1y - p0y, fz = p1z - p0z;
    const float axx = ey * fz - ez * fy;
    const float axy = ez * fx - ex * fz;
    const float axz = ex * fy - ey * fx;
    const float dp  = axx * d0x + axy * d0y + axz * d0z;
    const float sg  = (dp > 0.0f) ? 1.0f : ((dp < 0.0f) ? -1.0f : 0.0f);

    // c0 = d0 x d1, c1 = d1 x d3, c2 = d3 x d2, c3 = d2 x d0
    const float c0x = d0y * d1z - d0z * d1y;
    const float c0y = d0z * d1x - d0x * d1z;
    const float c0z = d0x * d1y - d0y * d1x;

    const float c1x = d1y * d3z - d1z * d3y;
    const float c1y = d1z * d3x - d1x * d3z;
    const float c1z = d1x * d3y - d1y * d3x;

    const float c2x = d3y * d2z - d3z * d2y;
    const float c2y = d3z * d2x - d3x * d2z;
    const float c2z = d3x * d2y - d3y * d2x;

    const float c3x = d2y * d0z - d2z * d0y;
    const float c3y = d2z * d0x - d2x * d0z;
    const float c3z = d2x * d0y - d2y * d0x;

    const float r0 = rsqrtf(c0x * c0x + c0y * c0y + c0z * c0z);
    const float r1 = rsqrtf(c1x * c1x + c1y * c1y + c1z * c1z);
    const float r2 = rsqrtf(c2x * c2x + c2y * c2y + c2z * c2z);
    const float r3 = rsqrtf(c3x * c3x + c3y * c3y + c3z * c3z);

    float q0 = (c0x * c1x + c0y * c1y + c0z * c1z) * r0 * r1;
    float q1 = (c1x * c2x + c1y * c2y + c1z * c2z) * r1 * r2;
    float q2 = (c2x * c3x + c2y * c3y + c2z * c3z) * r2 * r3;
    float q3 = (c3x * c0x + c3y * c0y + c3z * c0z) * r3 * r0;

    q0 = fminf(fmaxf(q0, -1.0f), 1.0f);
    q1 = fminf(fmaxf(q1, -1.0f), 1.0f);
    q2 = fminf(fmaxf(q2, -1.0f), 1.0f);
    q3 = fminf(fmaxf(q3, -1.0f), 1.0f);

    const float omega = asinf(q0) + asinf(q1) + asinf(q2) + asinf(q3);
    const float wr = omega * sg * 0.15915494309189535f; // 1/(2*pi)

    float* S = g_S + (size_t)b * SDIM * SDIM;
    S[(i + 1) * SDIM + (j + 1)] = wr;   // coalesced
    S[(j + 1) * SDIM + (i + 1)] = wr;   // transposed (scattered, absorbed by L2)
}

// -------------------------------------------------------------------------
// Kernel 2: streaming 2x2 stencil.
// out[b, k] with k <-> (r, c) row-major off-diagonal:
//   out = S[r][c] + S[r][c-1] + S[r-1][c] + S[r-1][c-1]
// (all via the zero-padded layout: padded coord (x+1, y+1))
// -------------------------------------------------------------------------
__global__ __launch_bounds__(256) void gather_kernel(float* __restrict__ out)
{
    const int k = blockIdx.x * blockDim.x + threadIdx.x;
    const int b = blockIdx.y;
    if (k >= OUTPB) return;

    const int r  = k / 127;
    const int cp = k - r * 127;
    const int c  = cp + (cp >= r ? 1 : 0);

    const float* S = g_S + (size_t)b * SDIM * SDIM;
    // padded coords: row (r+1) & r, col (c+1) & c
    const float* row1 = S + (r + 1) * SDIM;
    const float* row0 = S + r * SDIM;
    const float v = row1[c + 1] + row1[c] + row0[c + 1] + row0[c];

    out[(size_t)b * OUTPB + k] = v;
}

// -------------------------------------------------------------------------
extern "C" void kernel_launch(void* const* d_in, const int* in_sizes, int n_in,
                              void* d_out, int out_size)
{
    const float* xyz = (const float*)d_in[0];
    int B = in_sizes[0] / (NA * 3);
    if (B > MAXB) B = MAXB;

    dim3 gw((NSEG + 255) / 256, B);
    writhe_kernel<<<gw, 256>>>(xyz);

    dim3 gg((OUTPB + 255) / 256, B);
    gather_kernel<<<gg, 256>>>((float*)d_out);
}

// round 3
// speedup vs baseline: 1.2560x; 1.0060x over previous
#include <cuda_runtime.h>

// Problem constants (N_ATOMS = 128, fixed by the reference)
#define NA      128
#define NSEG    7875          // sum_{i=0}^{124} (125 - i)
#define OUTPB   16256         // n^2 - n  (all off-diagonal cells, row-major)
#define NQUADS  4064          // OUTPB / 4
#define THREADS 256
#define CHUNK   31            // ceil(NSEG / THREADS)

// off(i) = number of segments with first index < i  (n = 128)
__device__ __forceinline__ int seg_off(int i) { return (i * (251 - i)) >> 1; }

// Branch-free asin via Abramowitz & Stegun 4.4.46 (|eps| ~ 1e-7 in float)
__device__ __forceinline__ float fast_asin(float x)
{
    const float a = fabsf(x);
    float p = fmaf(a, -0.0012624911f, 0.0066700901f);
    p = fmaf(a, p, -0.0170881256f);
    p = fmaf(a, p,  0.0308918810f);
    p = fmaf(a, p, -0.0501743046f);
    p = fmaf(a, p,  0.0889789874f);
    p = fmaf(a, p, -0.2145988016f);
    p = fmaf(a, p,  1.5707963050f);
    const float om = 1.0f - a;                     // >= 0 (input clamped)
    const float s  = om * rsqrtf(fmaxf(om, 1e-38f)); // sqrt(om) via MUFU
    return copysignf(1.5707963268f - s * p, x);
}

// Triangle lookup with validity predicate: wr(min,max) or 0
__device__ __forceinline__ float look(const float* __restrict__ sh, int u, int v)
{
    const int x = min(u, v), y = max(u, v);
    const bool ok = (x >= 0) & (y <= 126) & ((y - x) >= 2);
    return ok ? sh[seg_off(x) + y - x - 2] : 0.0f;
}

// -------------------------------------------------------------------------
// Fused kernel: one block per batch.
// Phase 1: compute all 7875 segment writhes into shared memory.
// Phase 2: 2x2 symmetric stencil -> float4 coalesced output stores.
// -------------------------------------------------------------------------
__global__ __launch_bounds__(THREADS) void fused_kernel(const float* __restrict__ xyz,
                                                        float* __restrict__ out)
{
    __shared__ float sx[NA], sy[NA], sz[NA];
    __shared__ float sh_wr[NSEG];

    const int b   = blockIdx.x;
    const int tid = threadIdx.x;

    const float* x = xyz + (size_t)b * NA * 3;
    for (int t = tid; t < NA; t += THREADS) {
        sx[t] = x[3 * t + 0];
        sy[t] = x[3 * t + 1];
        sz[t] = x[3 * t + 2];
    }
    __syncthreads();

    // ---- Phase 1: contiguous chunk of segments per thread ----
    const int s0  = tid * CHUNK;
    const int cnt = min(CHUNK, NSEG - s0);

    if (cnt > 0) {
        // invert s0 -> (i, j) once, then walk incrementally
        int i = (int)((251.0f - sqrtf(63001.0f - 8.0f * (float)s0)) * 0.5f);
        if (i < 0) i = 0;
        if (i > 124) i = 124;
        while (i < 124 && seg_off(i + 1) <= s0) i++;
        while (i > 0 && seg_off(i) > s0) i--;
        int j = s0 - seg_off(i) + i + 2;

        for (int c = 0; c < cnt; ++c) {
            const float p0x = sx[i],     p0y = sy[i],     p0z = sz[i];
            const float p1x = sx[i + 1], p1y = sy[i + 1], p1z = sz[i + 1];
            const float p2x = sx[j],     p2y = sy[j],     p2z = sz[j];
            const float p3x = sx[j + 1], p3y = sy[j + 1], p3z = sz[j + 1];

            // unnormalized directions (normalization is redundant)
            const float d0x = p2x - p0x, d0y = p2y - p0y, d0z = p2z - p0z;
            const float d1x = p3x - p0x, d1y = p3y - p0y, d1z = p3z - p0z;
            const float d2x = p2x - p1x, d2y = p2y - p1y, d2z = p2z - p1z;
            const float d3x = p3x - p1x, d3y = p3y - p1y, d3z = p3z - p1z;

            // axial = cross(p3 - p2, p1 - p0); sign of dot(axial, d0)
            const float ex = p3x - p2x, ey = p3y - p2y, ez = p3z - p2z;
            const float fx = p1x - p0x, fy = p1y - p0y, fz = p1z - p0z;
            const float axx = ey * fz - ez * fy;
            const float axy = ez * fx - ex * fz;
            const float axz = ex * fy - ey * fx;
            const float dp  = axx * d0x + axy * d0y + axz * d0z;
            const float sg  = (dp > 0.0f) ? 1.0f : ((dp < 0.0f) ? -1.0f : 0.0f);

            // c0 = d0 x d1, c1 = d1 x d3, c2 = d3 x d2, c3 = d2 x d0
            const float c0x = d0y * d1z - d0z * d1y;
            const float c0y = d0z * d1x - d0x * d1z;
            const float c0z = d0x * d1y - d0y * d1x;

            const float c1x = d1y * d3z - d1z * d3y;
            const float c1y = d1z * d3x - d1x * d3z;
            const float c1z = d1x * d3y - d1y * d3x;

            const float c2x = d3y * d2z - d3z * d2y;
            const float c2y = d3z * d2x - d3x * d2z;
            const float c2z = d3x * d2y - d3y * d2x;

            const float c3x = d2y * d0z - d2z * d0y;
            const float c3y = d2z * d0x - d2x * d0z;
            const float c3z = d2x * d0y - d2y * d0x;

            const float r0 = rsqrtf(c0x * c0x + c0y * c0y + c0z * c0z);
            const float r1 = rsqrtf(c1x * c1x + c1y * c1y + c1z * c1z);
            const float r2 = rsqrtf(c2x * c2x + c2y * c2y + c2z * c2z);
            const float r3 = rsqrtf(c3x * c3x + c3y * c3y + c3z * c3z);

            float q0 = (c0x * c1x + c0y * c1y + c0z * c1z) * r0 * r1;
            float q1 = (c1x * c2x + c1y * c2y + c1z * c2z) * r1 * r2;
            float q2 = (c2x * c3x + c2y * c3y + c2z * c3z) * r2 * r3;
            float q3 = (c3x * c0x + c3y * c0y + c3z * c0z) * r3 * r0;

            q0 = fminf(fmaxf(q0, -1.0f), 1.0f);
            q1 = fminf(fmaxf(q1, -1.0f), 1.0f);
            q2 = fminf(fmaxf(q2, -1.0f), 1.0f);
            q3 = fminf(fmaxf(q3, -1.0f), 1.0f);

            const float omega = fast_asin(q0) + fast_asin(q1) +
                                fast_asin(q2) + fast_asin(q3);

            sh_wr[s0 + c] = omega * sg * 0.15915494309189535f; // 1/(2*pi)

            // advance (i, j)
            if (++j > 126) { ++i; j = i + 2; }
        }
    }
    __syncthreads();

    // ---- Phase 2: stencil gather from shared, float4 stores ----
    float4* outq = (float4*)(out + (size_t)b * OUTPB);
    #pragma unroll
    for (int it = 0; it < 16; ++it) {
        const int q = tid + it * THREADS;
        if (q < NQUADS) {
            float v[4];
            #pragma unroll
            for (int m = 0; m < 4; ++m) {
                const int k  = 4 * q + m;
                const int r  = k / 127;
                const int cp = k - r * 127;
                const int c  = cp + (cp >= r ? 1 : 0);
                v[m] = look(sh_wr, r, c)     + look(sh_wr, r, c - 1) +
                       look(sh_wr, r - 1, c) + look(sh_wr, r - 1, c - 1);
            }
            outq[q] = make_float4(v[0], v[1], v[2], v[3]);
        }
    }
}

// -------------------------------------------------------------------------
extern "C" void kernel_launch(void* const* d_in, const int* in_sizes, int n_in,
                              void* d_out, int out_size)
{
    const float* xyz = (const float*)d_in[0];
    const int B = in_sizes[0] / (NA * 3);

    fused_kernel<<<B, THREADS>>>(xyz, (float*)d_out);
}